// round 9
// baseline (speedup 1.0000x reference)
#include <cuda_runtime.h>
#include <cuda_bf16.h>
#include <math_constants.h>
#include <cstdint>

#define BB  4
#define SS  2048
#define DD  1024
#define HH  16
#define DHH 64

// ---------------- scratch (device globals; no allocations) ----------------
__device__ __nv_bfloat16 g_xh[(size_t)BB * SS * DD];
__device__ __nv_bfloat16 g_xl[(size_t)BB * SS * DD];
__device__ __nv_bfloat16 g_WqTh[(size_t)DD * DD], g_WqTl[(size_t)DD * DD];
__device__ __nv_bfloat16 g_WkTh[(size_t)DD * DD], g_WkTl[(size_t)DD * DD];
__device__ __nv_bfloat16 g_WvTh[(size_t)DD * DD], g_WvTl[(size_t)DD * DD];
__device__ __nv_bfloat16 g_WoTh[(size_t)DD * DD], g_WoTl[(size_t)DD * DD];
__device__ __nv_bfloat16 g_Qh[(size_t)BB * HH * SS * DHH], g_Ql[(size_t)BB * HH * SS * DHH];
__device__ __nv_bfloat16 g_Kh[(size_t)BB * HH * SS * DHH], g_Kl[(size_t)BB * HH * SS * DHH];
__device__ __nv_bfloat16 g_Vh[(size_t)BB * HH * SS * DHH], g_Vl[(size_t)BB * HH * SS * DHH];
__device__ __nv_bfloat16 g_Oh[(size_t)BB * SS * DD];
__device__ __nv_bfloat16 g_Ol[(size_t)BB * SS * DD];

// ---------------- PTX helpers (sm_80+ only) ----------------
__device__ __forceinline__ uint32_t s2u(const void* p) {
    uint32_t a;
    asm("{ .reg .u64 t; cvta.to.shared.u64 t, %1; cvt.u32.u64 %0, t; }"
        : "=r"(a) : "l"(p));
    return a;
}
__device__ __forceinline__ void ldsm4(uint32_t* r, uint32_t addr) {
    asm volatile("ldmatrix.sync.aligned.m8n8.x4.shared.b16 {%0,%1,%2,%3}, [%4];"
        : "=r"(r[0]), "=r"(r[1]), "=r"(r[2]), "=r"(r[3]) : "r"(addr));
}
__device__ __forceinline__ void ldsm4t(uint32_t* r, uint32_t addr) {
    asm volatile("ldmatrix.sync.aligned.m8n8.x4.trans.shared.b16 {%0,%1,%2,%3}, [%4];"
        : "=r"(r[0]), "=r"(r[1]), "=r"(r[2]), "=r"(r[3]) : "r"(addr));
}
__device__ __forceinline__ void ldsm2(uint32_t* r, uint32_t addr) {
    asm volatile("ldmatrix.sync.aligned.m8n8.x2.shared.b16 {%0,%1}, [%2];"
        : "=r"(r[0]), "=r"(r[1]) : "r"(addr));
}
__device__ __forceinline__ void mma_bf16(float* d, const uint32_t* a, const uint32_t* b) {
    asm volatile(
        "mma.sync.aligned.m16n8k16.row.col.f32.bf16.bf16.f32 "
        "{%0,%1,%2,%3}, {%4,%5,%6,%7}, {%8,%9}, {%0,%1,%2,%3};"
        : "+f"(d[0]), "+f"(d[1]), "+f"(d[2]), "+f"(d[3])
        : "r"(a[0]), "r"(a[1]), "r"(a[2]), "r"(a[3]), "r"(b[0]), "r"(b[1]));
}
__device__ __forceinline__ void cpa16(uint32_t s, const void* g) {
    asm volatile("cp.async.cg.shared.global [%0], [%1], 16;" :: "r"(s), "l"(g));
}
#define CPA_COMMIT() asm volatile("cp.async.commit_group;" ::: "memory")
#define CPA_WAIT(n)  asm volatile("cp.async.wait_group %0;" :: "n"(n) : "memory")

__device__ __forceinline__ uint32_t packbf(float x, float y) {
    __nv_bfloat162 t = __floats2bfloat162_rn(x, y);
    return *(uint32_t*)&t;
}
__device__ __forceinline__ void split2(float a, float b, uint32_t& h, uint32_t& l) {
    float ha = __bfloat162float(__float2bfloat16(a));
    float hb = __bfloat162float(__float2bfloat16(b));
    h = packbf(ha, hb);
    l = packbf(a - ha, b - hb);
}

// ---------------- bf16 hi/lo split kernels ----------------
__global__ __launch_bounds__(256) void split_x(const float* __restrict__ x) {
    size_t i = ((size_t)blockIdx.x * 256 + threadIdx.x) * 4;
    float4 v = *(const float4*)(x + i);
    float vv[4] = {v.x, v.y, v.z, v.w};
    __nv_bfloat16 h[4], l[4];
    #pragma unroll
    for (int j = 0; j < 4; j++) {
        h[j] = __float2bfloat16(vv[j]);
        l[j] = __float2bfloat16(vv[j] - __bfloat162float(h[j]));
    }
    *(uint2*)(g_xh + i) = *(uint2*)h;
    *(uint2*)(g_xl + i) = *(uint2*)l;
}

__global__ void transpose_split(const float* __restrict__ Wq, const float* __restrict__ Wk,
                                const float* __restrict__ Wv, const float* __restrict__ Wo) {
    __shared__ float t[32][33];
    const int z = blockIdx.z;
    const float* W = (z == 0) ? Wq : (z == 1) ? Wk : (z == 2) ? Wv : Wo;
    __nv_bfloat16* Th = (z == 0) ? g_WqTh : (z == 1) ? g_WkTh : (z == 2) ? g_WvTh : g_WoTh;
    __nv_bfloat16* Tl = (z == 0) ? g_WqTl : (z == 1) ? g_WkTl : (z == 2) ? g_WvTl : g_WoTl;
    const int n0 = blockIdx.x * 32, k0 = blockIdx.y * 32;
    const int tx = threadIdx.x, ty = threadIdx.y;
    #pragma unroll
    for (int j = 0; j < 32; j += 8)
        t[ty + j][tx] = W[(size_t)(k0 + ty + j) * DD + n0 + tx];
    __syncthreads();
    #pragma unroll
    for (int j = 0; j < 32; j += 8) {
        float v = t[tx][ty + j];
        int n = n0 + ty + j, k = k0 + tx;
        __nv_bfloat16 h = __float2bfloat16(v);
        __nv_bfloat16 l = __float2bfloat16(v - __bfloat162float(h));
        Th[(size_t)n * DD + k] = h;
        Tl[(size_t)n * DD + k] = l;
    }
}

// ---------------- mma.sync GEMM: 128x128 tile, bf16x3, cp.async ------------
#define KCH     32
#define NCHUNK  (DD / KCH)
#define RSTR    40
#define TILE_B  (128 * RSTR * 2)
#define BUF_B   (4 * TILE_B)
#define GEMM_SMEM (2 * BUF_B)

__device__ __forceinline__ void gemm_loop(
    const __nv_bfloat16* __restrict__ Ah, const __nv_bfloat16* __restrict__ Al,
    const __nv_bfloat16* __restrict__ Bh, const __nv_bfloat16* __restrict__ Bl,
    int m0, int n0, char* sm, float acc[4][4][4])
{
    const int tid  = threadIdx.x;
    const int lane = tid & 31;
    const int warp = tid >> 5;
    const int wm   = warp & 1;
    const int wn   = warp >> 1;

    const uint32_t sb = s2u(sm);
    const int a_row = wm * 64 + (lane & 7) + ((lane >> 3) & 1) * 8;
    const int a_kof = (lane >> 4) * 8;
    const int b_row = wn * 32 + (lane & 7);
    const int b_kof = ((lane >> 3) & 1) * 8;

    auto issue = [&](int k0, uint32_t dstb) {
        #pragma unroll
        for (int it = 0; it < 8; it++) {
            int gid  = it * 256 + tid;       // 0..2047
            int tile = gid >> 9;             // 0..3 (compile-time after unroll)
            int row  = (gid >> 2) & 127;
            int seg  = gid & 3;
            const __nv_bfloat16* src = (tile == 0) ? Ah : (tile == 1) ? Al
                                     : (tile == 2) ? Bh : Bl;
            int rb = (tile < 2) ? m0 : n0;
            cpa16(dstb + (uint32_t)tile * TILE_B + (uint32_t)(row * RSTR + seg * 8) * 2,
                  src + (size_t)(rb + row) * DD + k0 + seg * 8);
        }
        CPA_COMMIT();
    };

    issue(0, sb);

    for (int c = 0; c < NCHUNK; c++) {
        CPA_WAIT(0);              // buffer c&1 ready
        __syncthreads();          // publish to all warps; all done with buf (c+1)&1
        if (c + 1 < NCHUNK)       // copy(c+1) overlaps compute(c)
            issue((c + 1) * KCH, sb + (uint32_t)((c + 1) & 1) * BUF_B);

        const uint32_t bufb = sb + (uint32_t)(c & 1) * BUF_B;
        #pragma unroll
        for (int ks = 0; ks < 2; ks++) {
            uint32_t fbh[4][2], fbl[4][2];
            #pragma unroll
            for (int ni = 0; ni < 4; ni++) {
                uint32_t bo = bufb + (uint32_t)(((b_row + ni * 8) * RSTR) + ks * 16 + b_kof) * 2;
                ldsm2(fbh[ni], bo + 2 * TILE_B);
                ldsm2(fbl[ni], bo + 3 * TILE_B);
            }
            #pragma unroll
            for (int mi = 0; mi < 4; mi++) {
                uint32_t fah[4], fal[4];
                uint32_t ao = bufb + (uint32_t)(((a_row + mi * 16) * RSTR) + ks * 16 + a_kof) * 2;
                ldsm4(fah, ao);
                ldsm4(fal, ao + TILE_B);
                #pragma unroll
                for (int ni = 0; ni < 4; ni++) {
                    mma_bf16(acc[mi][ni], fah, fbh[ni]);
                    mma_bf16(acc[mi][ni], fah, fbl[ni]);
                    mma_bf16(acc[mi][ni], fal, fbh[ni]);
                }
            }
        }
    }
}

// ---------------- projection GEMMs (Q/K/V) -> bf16 hi/lo ----------------
__global__ __launch_bounds__(256, 2) void proj_tc(const float* __restrict__ bq,
                                                  const float* __restrict__ bk,
                                                  const float* __restrict__ bv)
{
    extern __shared__ char sm[];
    const int z = blockIdx.z;
    const __nv_bfloat16* Bh = (z == 0) ? g_WqTh : (z == 1) ? g_WkTh : g_WvTh;
    const __nv_bfloat16* Bl = (z == 0) ? g_WqTl : (z == 1) ? g_WkTl : g_WvTl;
    const float* bias       = (z == 0) ? bq : (z == 1) ? bk : bv;
    __nv_bfloat16* Oh       = (z == 0) ? g_Qh : (z == 1) ? g_Kh : g_Vh;
    __nv_bfloat16* Ol       = (z == 0) ? g_Ql : (z == 1) ? g_Kl : g_Vl;

    const int m0 = blockIdx.y * 128;
    const int n0 = blockIdx.x * 128;

    float acc[4][4][4];
    #pragma unroll
    for (int mi = 0; mi < 4; mi++)
        #pragma unroll
        for (int ni = 0; ni < 4; ni++)
            #pragma unroll
            for (int k = 0; k < 4; k++) acc[mi][ni][k] = 0.f;

    gemm_loop(g_xh, g_xl, Bh, Bl, m0, n0, sm, acc);

    const int lane = threadIdx.x & 31;
    const int warp = threadIdx.x >> 5;
    const int wm = warp & 1, wn = warp >> 1;

    #pragma unroll
    for (int ni = 0; ni < 4; ni++) {
        const int gn = n0 + wn * 32 + ni * 8 + (lane & 3) * 2;
        const int h = gn >> 6, dh = gn & 63;
        const float b0 = bias[gn], b1 = bias[gn + 1];
        #pragma unroll
        for (int mi = 0; mi < 4; mi++) {
            const int gm = m0 + wm * 64 + mi * 16 + (lane >> 2);
            #pragma unroll
            for (int rh = 0; rh < 2; rh++) {
                const int m = gm + rh * 8;
                const int bidx = m >> 11, s = m & 2047;
                float vx = acc[mi][ni][rh * 2 + 0] + b0;
                float vy = acc[mi][ni][rh * 2 + 1] + b1;
                uint32_t uh, ul;
                split2(vx, vy, uh, ul);
                size_t idx = (((size_t)bidx * HH + h) * SS + s) * DHH + dh;
                *(uint32_t*)(Oh + idx) = uh;
                *(uint32_t*)(Ol + idx) = ul;
            }
        }
    }
}

// ---------------- output projection ----------------
__global__ __launch_bounds__(256, 2) void outproj_tc(const float* __restrict__ bo,
                                                     float* __restrict__ out)
{
    extern __shared__ char sm[];
    const int m0 = blockIdx.y * 128;
    const int n0 = blockIdx.x * 128;

    float acc[4][4][4];
    #pragma unroll
    for (int mi = 0; mi < 4; mi++)
        #pragma unroll
        for (int ni = 0; ni < 4; ni++)
            #pragma unroll
            for (int k = 0; k < 4; k++) acc[mi][ni][k] = 0.f;

    gemm_loop(g_Oh, g_Ol, g_WoTh, g_WoTl, m0, n0, sm, acc);

    const int lane = threadIdx.x & 31;
    const int warp = threadIdx.x >> 5;
    const int wm = warp & 1, wn = warp >> 1;

    #pragma unroll
    for (int ni = 0; ni < 4; ni++) {
        const int gn = n0 + wn * 32 + ni * 8 + (lane & 3) * 2;
        const float b0 = bo[gn], b1 = bo[gn + 1];
        #pragma unroll
        for (int mi = 0; mi < 4; mi++) {
            const int gm = m0 + wm * 64 + mi * 16 + (lane >> 2);
            #pragma unroll
            for (int rh = 0; rh < 2; rh++) {
                const int m = gm + rh * 8;
                float2 v;
                v.x = acc[mi][ni][rh * 2 + 0] + b0;
                v.y = acc[mi][ni][rh * 2 + 1] + b1;
                *(float2*)(out + (size_t)m * DD + gn) = v;
            }
        }
    }
}

// ---------------- tensor-core attention, faithful recurrence ----------------
#define TSTR_B   144
#define TILE_KV  (64 * TSTR_B)        // 9216
#define OFF_KH   (2 * TILE_KV)
#define OFF_VH   (4 * TILE_KV)
#define ATT_SMEM (6 * TILE_KV)        // 55296

__global__ __launch_bounds__(128, 3) void attn_tc()
{
    extern __shared__ char sm[];
    const int qt = blockIdx.x;
    const int q0 = qt * 64;
    const int bh = blockIdx.y;
    const size_t base = (size_t)bh * SS * DHH;
    const __nv_bfloat16* __restrict__ Qh = g_Qh + base;
    const __nv_bfloat16* __restrict__ Ql = g_Ql + base;
    const __nv_bfloat16* __restrict__ Kh = g_Kh + base;
    const __nv_bfloat16* __restrict__ Kl = g_Kl + base;
    const __nv_bfloat16* __restrict__ Vh = g_Vh + base;
    const __nv_bfloat16* __restrict__ Vl = g_Vl + base;

    const int tid  = threadIdx.x;
    const int lane = tid & 31;
    const int warp = tid >> 5;
    const uint32_t smb = s2u(sm);

    auto issue_pair = [&](const __nv_bfloat16* Sh, const __nv_bfloat16* Sl,
                          uint32_t dstb, int j) {
        #pragma unroll
        for (int it = 0; it < 8; it++) {
            int s = it * 128 + tid;
            int half = s >> 9;
            int row = (s >> 3) & 63;
            int seg = s & 7;
            cpa16(dstb + (uint32_t)half * TILE_KV + (uint32_t)(row * TSTR_B + seg * 16),
                  (half ? Sl : Sh) + (size_t)(j * 64 + row) * DHH + seg * 8);
        }
        CPA_COMMIT();
    };

    #pragma unroll
    for (int it = 0; it < 4; it++) {
        int s = it * 128 + tid;
        int row = s >> 3, seg = s & 7;
        *(uint4*)(sm + row * TSTR_B + seg * 16) =
            *(const uint4*)(Qh + (size_t)(q0 + row) * DHH + seg * 8);
        *(uint4*)(sm + TILE_KV + row * TSTR_B + seg * 16) =
            *(const uint4*)(Ql + (size_t)(q0 + row) * DHH + seg * 8);
    }
    issue_pair(Kh, Kl, smb + OFF_KH, 0);
    issue_pair(Vh, Vl, smb + OFF_VH, 0);
    __syncthreads();

    uint32_t qfh[4][4], qfl[4][4];
    {
        uint32_t qa = smb + (uint32_t)((warp * 16 + (lane & 7) + ((lane >> 3) & 1) * 8) * TSTR_B
                                       + ((lane >> 4) & 1) * 16);
        #pragma unroll
        for (int ks = 0; ks < 4; ks++) {
            ldsm4(qfh[ks], qa + ks * 32);
            ldsm4(qfl[ks], qa + ks * 32 + TILE_KV);
        }
    }

    float o[8][4];
    #pragma unroll
    for (int nb = 0; nb < 8; nb++)
        #pragma unroll
        for (int r = 0; r < 4; r++) o[nb][r] = 0.f;
    float m0s = -CUDART_INF_F, m1s = -CUDART_INF_F, l0s = 0.f, l1s = 0.f;

    const int qlo = q0 + warp * 16 + (lane >> 2);
    const int qhi = qlo + 8;

    for (int j = 0; j <= qt; j++) {
        CPA_WAIT(1);              // K(j) ready; V(j) may be in flight
        __syncthreads();

        float c[8][4];
        #pragma unroll
        for (int nb = 0; nb < 8; nb++)
            #pragma unroll
            for (int r = 0; r < 4; r++) c[nb][r] = 0.f;

        #pragma unroll
        for (int ks = 0; ks < 4; ks++) {
            uint32_t kfh[4][4], kfl[4][4];
            #pragma unroll
            for (int p = 0; p < 4; p++) {
                uint32_t ka = smb + OFF_KH
                            + (uint32_t)((p * 16 + (lane & 7) + ((lane >> 4) & 1) * 8) * TSTR_B
                                         + ((lane >> 3) & 1) * 16 + ks * 32);
                ldsm4(kfh[p], ka);
                ldsm4(kfl[p], ka + TILE_KV);
            }
            #pragma unroll
            for (int p = 0; p < 4; p++)
                #pragma unroll
                for (int h2 = 0; h2 < 2; h2++) {
                    int nb = p * 2 + h2;
                    mma_bf16(c[nb], qfh[ks], &kfh[p][h2 * 2]);
                    mma_bf16(c[nb], qfh[ks], &kfl[p][h2 * 2]);
                    mma_bf16(c[nb], qfl[ks], &kfh[p][h2 * 2]);
                }
        }
        __syncthreads();
        if (j < qt) issue_pair(Kh, Kl, smb + OFF_KH, j + 1);

        const bool diag = (j == qt);
        float mx0 = -CUDART_INF_F, mx1 = -CUDART_INF_F;
        #pragma unroll
        for (int nb = 0; nb < 8; nb++) {
            #pragma unroll
            for (int r = 0; r < 4; r++) c[nb][r] *= 0.125f;
            if (diag) {
                int colb = j * 64 + nb * 8 + (lane & 3) * 2;
                if (colb     > qlo) c[nb][0] = -CUDART_INF_F;
                if (colb + 1 > qlo) c[nb][1] = -CUDART_INF_F;
                if (colb     > qhi) c[nb][2] = -CUDART_INF_F;
                if (colb + 1 > qhi) c[nb][3] = -CUDART_INF_F;
            }
            mx0 = fmaxf(mx0, fmaxf(c[nb][0], c[nb][1]));
            mx1 = fmaxf(mx1, fmaxf(c[nb][2], c[nb][3]));
        }
        mx0 = fmaxf(mx0, __shfl_xor_sync(0xffffffffu, mx0, 1));
        mx0 = fmaxf(mx0, __shfl_xor_sync(0xffffffffu, mx0, 2));
        mx1 = fmaxf(mx1, __shfl_xor_sync(0xffffffffu, mx1, 1));
        mx1 = fmaxf(mx1, __shfl_xor_sync(0xffffffffu, mx1, 2));

        const float mn0 = fmaxf(m0s, mx0), mn1 = fmaxf(m1s, mx1);
        float s0 = 0.f, s1 = 0.f;
        #pragma unroll
        for (int nb = 0; nb < 8; nb++) {
            c[nb][0] = __expf(c[nb][0] - mn0);
            c[nb][1] = __expf(c[nb][1] - mn0);
            c[nb][2] = __expf(c[nb][2] - mn1);
            c[nb][3] = __expf(c[nb][3] - mn1);
            s0 += c[nb][0] + c[nb][1];
            s1 += c[nb][2] + c[nb][3];
        }
        s0 += __shfl_xor_sync(0xffffffffu, s0, 1);
        s0 += __shfl_xor_sync(0xffffffffu, s0, 2);
        s1 += __shfl_xor_sync(0xffffffffu, s1, 1);
        s1 += __shfl_xor_sync(0xffffffffu, s1, 2);

        const float a0 = __expf(m0s - mn0), a1 = __expf(m1s - mn1);
        const float ln0 = a0 * l0s + s0, ln1 = a1 * l1s + s1;
        const float f0 = l0s / ln0 * a0, f1 = l1s / ln1 * a1;
        #pragma unroll
        for (int nb = 0; nb < 8; nb++) {
            o[nb][0] *= f0; o[nb][1] *= f0;
            o[nb][2] *= f1; o[nb][3] *= f1;
        }
        m0s = mn0; l0s = ln0; m1s = mn1; l1s = ln1;

        if (j < qt) { CPA_WAIT(1); } else { CPA_WAIT(0); }
        __syncthreads();

        #pragma unroll
        for (int ks = 0; ks < 4; ks++) {
            uint32_t pah[4], pal[4];
            split2(c[2 * ks][0],     c[2 * ks][1],     pah[0], pal[0]);
            split2(c[2 * ks][2],     c[2 * ks][3],     pah[1], pal[1]);
            split2(c[2 * ks + 1][0], c[2 * ks + 1][1], pah[2], pal[2]);
            split2(c[2 * ks + 1][2], c[2 * ks + 1][3], pah[3], pal[3]);

            uint32_t vfh[4][4], vfl[4][4];
            #pragma unroll
            for (int p = 0; p < 4; p++) {
                uint32_t va = smb + OFF_VH
                            + (uint32_t)((ks * 16 + (lane & 7) + ((lane >> 3) & 1) * 8) * TSTR_B
                                         + (p * 16 + ((lane >> 4) & 1) * 8) * 2);
                ldsm4t(vfh[p], va);
                ldsm4t(vfl[p], va + TILE_KV);
            }
            #pragma unroll
            for (int p = 0; p < 4; p++)
                #pragma unroll
                for (int h2 = 0; h2 < 2; h2++) {
                    int nb = p * 2 + h2;
                    mma_bf16(o[nb], pah, &vfh[p][h2 * 2]);
                    mma_bf16(o[nb], pah, &vfl[p][h2 * 2]);
                    mma_bf16(o[nb], pal, &vfh[p][h2 * 2]);
                }
        }
        __syncthreads();
        if (j < qt) issue_pair(Vh, Vl, smb + OFF_VH, j + 1);
    }

    const int b = bh >> 4, hq = bh & 15;
    #pragma unroll
    for (int nb = 0; nb < 8; nb++) {
        const int col = hq * 64 + nb * 8 + (lane & 3) * 2;
        uint32_t ph, pl;
        split2(o[nb][0], o[nb][1], ph, pl);
        size_t idx = ((size_t)b * SS + qlo) * DD + col;
        *(uint32_t*)(g_Oh + idx) = ph;
        *(uint32_t*)(g_Ol + idx) = pl;
        split2(o[nb][2], o[nb][3], ph, pl);
        idx = ((size_t)b * SS + qhi) * DD + col;
        *(uint32_t*)(g_Oh + idx) = ph;
        *(uint32_t*)(g_Ol + idx) = pl;
    }
}

// ---------------- launch ----------------
extern "C" void kernel_launch(void* const* d_in, const int* in_sizes, int n_in,
                              void* d_out, int out_size)
{
    const float* x  = (const float*)d_in[0];
    const float* Wq = (const float*)d_in[1];
    const float* bq = (const float*)d_in[2];
    const float* Wk = (const float*)d_in[3];
    const float* bk = (const float*)d_in[4];
    const float* Wv = (const float*)d_in[5];
    const float* bv = (const float*)d_in[6];
    const float* Wo = (const float*)d_in[7];
    const float* bo = (const float*)d_in[8];
    float* out = (float*)d_out;

    static bool attr_done = false;
    if (!attr_done) {
        cudaFuncSetAttribute(attn_tc,
                             cudaFuncAttributeMaxDynamicSharedMemorySize, ATT_SMEM);
        cudaFuncSetAttribute(proj_tc,
                             cudaFuncAttributeMaxDynamicSharedMemorySize, GEMM_SMEM);
        cudaFuncSetAttribute(outproj_tc,
                             cudaFuncAttributeMaxDynamicSharedMemorySize, GEMM_SMEM);
        attr_done = true;
    }

    split_x<<<(BB * SS * DD) / (256 * 4), 256>>>(x);
    transpose_split<<<dim3(DD / 32, DD / 32, 4), dim3(32, 8)>>>(Wq, Wk, Wv, Wo);
    proj_tc<<<dim3(DD / 128, (BB * SS) / 128, 3), 256, GEMM_SMEM>>>(bq, bk, bv);
    attn_tc<<<dim3(SS / 64, BB * HH), 128, ATT_SMEM>>>();
    outproj_tc<<<dim3(DD / 128, (BB * SS) / 128), 256, GEMM_SMEM>>>(bo, out);
}

// round 10
// speedup vs baseline: 1.0799x; 1.0799x over previous
#include <cuda_runtime.h>
#include <cuda_bf16.h>
#include <math_constants.h>
#include <cstdint>

#define BB  4
#define SS  2048
#define DD  1024
#define HH  16
#define DHH 64

// ---------------- scratch (device globals; no allocations) ----------------
__device__ __nv_bfloat16 g_xh[(size_t)BB * SS * DD];
__device__ __nv_bfloat16 g_xl[(size_t)BB * SS * DD];
__device__ __nv_bfloat16 g_WqTh[(size_t)DD * DD], g_WqTl[(size_t)DD * DD];
__device__ __nv_bfloat16 g_WkTh[(size_t)DD * DD], g_WkTl[(size_t)DD * DD];
__device__ __nv_bfloat16 g_WvTh[(size_t)DD * DD], g_WvTl[(size_t)DD * DD];
__device__ __nv_bfloat16 g_WoTh[(size_t)DD * DD], g_WoTl[(size_t)DD * DD];
__device__ __nv_bfloat16 g_Qh[(size_t)BB * HH * SS * DHH], g_Ql[(size_t)BB * HH * SS * DHH];
__device__ __nv_bfloat16 g_Kh[(size_t)BB * HH * SS * DHH], g_Kl[(size_t)BB * HH * SS * DHH];
__device__ __nv_bfloat16 g_Vh[(size_t)BB * HH * SS * DHH], g_Vl[(size_t)BB * HH * SS * DHH];
__device__ __nv_bfloat16 g_Oh[(size_t)BB * SS * DD];
__device__ __nv_bfloat16 g_Ol[(size_t)BB * SS * DD];

// ---------------- PTX helpers (sm_80+ only) ----------------
__device__ __forceinline__ uint32_t s2u(const void* p) {
    uint32_t a;
    asm("{ .reg .u64 t; cvta.to.shared.u64 t, %1; cvt.u32.u64 %0, t; }"
        : "=r"(a) : "l"(p));
    return a;
}
__device__ __forceinline__ void ldsm4(uint32_t* r, uint32_t addr) {
    asm volatile("ldmatrix.sync.aligned.m8n8.x4.shared.b16 {%0,%1,%2,%3}, [%4];"
        : "=r"(r[0]), "=r"(r[1]), "=r"(r[2]), "=r"(r[3]) : "r"(addr));
}
__device__ __forceinline__ void ldsm4t(uint32_t* r, uint32_t addr) {
    asm volatile("ldmatrix.sync.aligned.m8n8.x4.trans.shared.b16 {%0,%1,%2,%3}, [%4];"
        : "=r"(r[0]), "=r"(r[1]), "=r"(r[2]), "=r"(r[3]) : "r"(addr));
}
__device__ __forceinline__ void mma_bf16(float* d, const uint32_t* a, const uint32_t* b) {
    asm volatile(
        "mma.sync.aligned.m16n8k16.row.col.f32.bf16.bf16.f32 "
        "{%0,%1,%2,%3}, {%4,%5,%6,%7}, {%8,%9}, {%0,%1,%2,%3};"
        : "+f"(d[0]), "+f"(d[1]), "+f"(d[2]), "+f"(d[3])
        : "r"(a[0]), "r"(a[1]), "r"(a[2]), "r"(a[3]), "r"(b[0]), "r"(b[1]));
}
__device__ __forceinline__ void cpa16(uint32_t s, const void* g) {
    asm volatile("cp.async.cg.shared.global [%0], [%1], 16;" :: "r"(s), "l"(g));
}
#define CPA_COMMIT() asm volatile("cp.async.commit_group;" ::: "memory")
#define CPA_WAIT(n)  asm volatile("cp.async.wait_group %0;" :: "n"(n) : "memory")

__device__ __forceinline__ uint32_t packbf(float x, float y) {
    __nv_bfloat162 t = __floats2bfloat162_rn(x, y);
    return *(uint32_t*)&t;
}
__device__ __forceinline__ void split2(float a, float b, uint32_t& h, uint32_t& l) {
    float ha = __bfloat162float(__float2bfloat16(a));
    float hb = __bfloat162float(__float2bfloat16(b));
    h = packbf(ha, hb);
    l = packbf(a - ha, b - hb);
}

// ---------------- bf16 hi/lo split kernels ----------------
__global__ __launch_bounds__(256) void split_x(const float* __restrict__ x) {
    size_t i = ((size_t)blockIdx.x * 256 + threadIdx.x) * 4;
    float4 v = *(const float4*)(x + i);
    float vv[4] = {v.x, v.y, v.z, v.w};
    __nv_bfloat16 h[4], l[4];
    #pragma unroll
    for (int j = 0; j < 4; j++) {
        h[j] = __float2bfloat16(vv[j]);
        l[j] = __float2bfloat16(vv[j] - __bfloat162float(h[j]));
    }
    *(uint2*)(g_xh + i) = *(uint2*)h;
    *(uint2*)(g_xl + i) = *(uint2*)l;
}

__global__ void transpose_split(const float* __restrict__ Wq, const float* __restrict__ Wk,
                                const float* __restrict__ Wv, const float* __restrict__ Wo) {
    __shared__ float t[32][33];
    const int z = blockIdx.z;
    const float* W = (z == 0) ? Wq : (z == 1) ? Wk : (z == 2) ? Wv : Wo;
    __nv_bfloat16* Th = (z == 0) ? g_WqTh : (z == 1) ? g_WkTh : (z == 2) ? g_WvTh : g_WoTh;
    __nv_bfloat16* Tl = (z == 0) ? g_WqTl : (z == 1) ? g_WkTl : (z == 2) ? g_WvTl : g_WoTl;
    const int n0 = blockIdx.x * 32, k0 = blockIdx.y * 32;
    const int tx = threadIdx.x, ty = threadIdx.y;
    #pragma unroll
    for (int j = 0; j < 32; j += 8)
        t[ty + j][tx] = W[(size_t)(k0 + ty + j) * DD + n0 + tx];
    __syncthreads();
    #pragma unroll
    for (int j = 0; j < 32; j += 8) {
        float v = t[tx][ty + j];
        int n = n0 + ty + j, k = k0 + tx;
        __nv_bfloat16 h = __float2bfloat16(v);
        __nv_bfloat16 l = __float2bfloat16(v - __bfloat162float(h));
        Th[(size_t)n * DD + k] = h;
        Tl[(size_t)n * DD + k] = l;
    }
}

// ---------------- mma.sync GEMM: 128x128 tile, bf16x3, cp.async ------------
#define KCH     32
#define NCHUNK  (DD / KCH)
#define RSTR    40
#define TILE_B  (128 * RSTR * 2)
#define BUF_B   (4 * TILE_B)
#define GEMM_SMEM (2 * BUF_B)

__device__ __forceinline__ void gemm_loop(
    const __nv_bfloat16* __restrict__ Ah, const __nv_bfloat16* __restrict__ Al,
    const __nv_bfloat16* __restrict__ Bh, const __nv_bfloat16* __restrict__ Bl,
    int m0, int n0, char* sm, float acc[4][4][4])
{
    const int tid  = threadIdx.x;
    const int lane = tid & 31;
    const int warp = tid >> 5;
    const int wm   = warp & 1;
    const int wn   = warp >> 1;

    const uint32_t sb = s2u(sm);
    const int a_row  = wm * 64 + (lane & 7) + ((lane >> 3) & 1) * 8;
    const int a_kof  = (lane >> 4) * 8;
    // B via ldsm4 pairs: 16 n-rows x 16 k per instruction
    const int b_row4 = wn * 32 + (lane & 7) + ((lane >> 4) & 1) * 8;
    const int b_kof4 = ((lane >> 3) & 1) * 8;

    auto issue = [&](int k0, uint32_t dstb) {
        #pragma unroll
        for (int it = 0; it < 8; it++) {
            int gid  = it * 256 + tid;       // 0..2047
            int tile = gid >> 9;             // 0..3 (compile-time after unroll)
            int row  = (gid >> 2) & 127;
            int seg  = gid & 3;
            const __nv_bfloat16* src = (tile == 0) ? Ah : (tile == 1) ? Al
                                     : (tile == 2) ? Bh : Bl;
            int rb = (tile < 2) ? m0 : n0;
            cpa16(dstb + (uint32_t)tile * TILE_B + (uint32_t)(row * RSTR + seg * 8) * 2,
                  src + (size_t)(rb + row) * DD + k0 + seg * 8);
        }
        CPA_COMMIT();
    };

    issue(0, sb);

    for (int c = 0; c < NCHUNK; c++) {
        CPA_WAIT(0);              // buffer c&1 ready
        __syncthreads();          // publish; all warps done with buf (c+1)&1
        if (c + 1 < NCHUNK)       // copy(c+1) overlaps compute(c)
            issue((c + 1) * KCH, sb + (uint32_t)((c + 1) & 1) * BUF_B);

        const uint32_t bufb = sb + (uint32_t)(c & 1) * BUF_B;
        #pragma unroll
        for (int ks = 0; ks < 2; ks++) {
            uint32_t fbh[4][2], fbl[4][2];
            #pragma unroll
            for (int nip = 0; nip < 2; nip++) {
                uint32_t bo = bufb + (uint32_t)(((b_row4 + nip * 16) * RSTR) + ks * 16 + b_kof4) * 2;
                uint32_t t4[4];
                ldsm4(t4, bo + 2 * TILE_B);
                fbh[nip * 2][0] = t4[0]; fbh[nip * 2][1] = t4[1];
                fbh[nip * 2 + 1][0] = t4[2]; fbh[nip * 2 + 1][1] = t4[3];
                ldsm4(t4, bo + 3 * TILE_B);
                fbl[nip * 2][0] = t4[0]; fbl[nip * 2][1] = t4[1];
                fbl[nip * 2 + 1][0] = t4[2]; fbl[nip * 2 + 1][1] = t4[3];
            }
            #pragma unroll
            for (int mi = 0; mi < 4; mi++) {
                uint32_t fah[4], fal[4];
                uint32_t ao = bufb + (uint32_t)(((a_row + mi * 16) * RSTR) + ks * 16 + a_kof) * 2;
                ldsm4(fah, ao);
                ldsm4(fal, ao + TILE_B);
                #pragma unroll
                for (int ni = 0; ni < 4; ni++) {
                    mma_bf16(acc[mi][ni], fah, fbh[ni]);
                    mma_bf16(acc[mi][ni], fah, fbl[ni]);
                    mma_bf16(acc[mi][ni], fal, fbh[ni]);
                }
            }
        }
    }
}

// ---------------- projection GEMMs (Q/K/V) -> bf16 hi/lo ----------------
__global__ __launch_bounds__(256, 2) void proj_tc(const float* __restrict__ bq,
                                                  const float* __restrict__ bk,
                                                  const float* __restrict__ bv)
{
    extern __shared__ char sm[];
    const int z = blockIdx.z;
    const __nv_bfloat16* Bh = (z == 0) ? g_WqTh : (z == 1) ? g_WkTh : g_WvTh;
    const __nv_bfloat16* Bl = (z == 0) ? g_WqTl : (z == 1) ? g_WkTl : g_WvTl;
    const float* bias       = (z == 0) ? bq : (z == 1) ? bk : bv;
    __nv_bfloat16* Oh       = (z == 0) ? g_Qh : (z == 1) ? g_Kh : g_Vh;
    __nv_bfloat16* Ol       = (z == 0) ? g_Ql : (z == 1) ? g_Kl : g_Vl;

    const int m0 = blockIdx.y * 128;
    const int n0 = blockIdx.x * 128;

    float acc[4][4][4];
    #pragma unroll
    for (int mi = 0; mi < 4; mi++)
        #pragma unroll
        for (int ni = 0; ni < 4; ni++)
            #pragma unroll
            for (int k = 0; k < 4; k++) acc[mi][ni][k] = 0.f;

    gemm_loop(g_xh, g_xl, Bh, Bl, m0, n0, sm, acc);

    const int lane = threadIdx.x & 31;
    const int warp = threadIdx.x >> 5;
    const int wm = warp & 1, wn = warp >> 1;

    #pragma unroll
    for (int ni = 0; ni < 4; ni++) {
        const int gn = n0 + wn * 32 + ni * 8 + (lane & 3) * 2;
        const int h = gn >> 6, dh = gn & 63;
        const float b0 = bias[gn], b1 = bias[gn + 1];
        #pragma unroll
        for (int mi = 0; mi < 4; mi++) {
            const int gm = m0 + wm * 64 + mi * 16 + (lane >> 2);
            #pragma unroll
            for (int rh = 0; rh < 2; rh++) {
                const int m = gm + rh * 8;
                const int bidx = m >> 11, s = m & 2047;
                float vx = acc[mi][ni][rh * 2 + 0] + b0;
                float vy = acc[mi][ni][rh * 2 + 1] + b1;
                uint32_t uh, ul;
                split2(vx, vy, uh, ul);
                size_t idx = (((size_t)bidx * HH + h) * SS + s) * DHH + dh;
                *(uint32_t*)(Oh + idx) = uh;
                *(uint32_t*)(Ol + idx) = ul;
            }
        }
    }
}

// ---------------- output projection ----------------
__global__ __launch_bounds__(256, 2) void outproj_tc(const float* __restrict__ bo,
                                                     float* __restrict__ out)
{
    extern __shared__ char sm[];
    const int m0 = blockIdx.y * 128;
    const int n0 = blockIdx.x * 128;

    float acc[4][4][4];
    #pragma unroll
    for (int mi = 0; mi < 4; mi++)
        #pragma unroll
        for (int ni = 0; ni < 4; ni++)
            #pragma unroll
            for (int k = 0; k < 4; k++) acc[mi][ni][k] = 0.f;

    gemm_loop(g_Oh, g_Ol, g_WoTh, g_WoTl, m0, n0, sm, acc);

    const int lane = threadIdx.x & 31;
    const int warp = threadIdx.x >> 5;
    const int wm = warp & 1, wn = warp >> 1;

    #pragma unroll
    for (int ni = 0; ni < 4; ni++) {
        const int gn = n0 + wn * 32 + ni * 8 + (lane & 3) * 2;
        const float b0 = bo[gn], b1 = bo[gn + 1];
        #pragma unroll
        for (int mi = 0; mi < 4; mi++) {
            const int gm = m0 + wm * 64 + mi * 16 + (lane >> 2);
            #pragma unroll
            for (int rh = 0; rh < 2; rh++) {
                const int m = gm + rh * 8;
                float2 v;
                v.x = acc[mi][ni][rh * 2 + 0] + b0;
                v.y = acc[mi][ni][rh * 2 + 1] + b1;
                *(float2*)(out + (size_t)m * DD + gn) = v;
            }
        }
    }
}

// ---------------- tensor-core attention, faithful recurrence ----------------
// Heavy-first: grid (x=bh, y=qt-index), qt = gridDim.y-1-blockIdx.y, so the
// 32-iteration CTAs launch first and light ones pack the tail.
#define TSTR_B   144
#define TILE_KV  (64 * TSTR_B)        // 9216
#define OFF_KH   (2 * TILE_KV)
#define OFF_VH   (4 * TILE_KV)
#define ATT_SMEM (6 * TILE_KV)        // 55296

__global__ __launch_bounds__(128, 3) void attn_tc()
{
    extern __shared__ char sm[];
    const int qt = (int)gridDim.y - 1 - (int)blockIdx.y;
    const int q0 = qt * 64;
    const int bh = blockIdx.x;
    const size_t base = (size_t)bh * SS * DHH;
    const __nv_bfloat16* __restrict__ Qh = g_Qh + base;
    const __nv_bfloat16* __restrict__ Ql = g_Ql + base;
    const __nv_bfloat16* __restrict__ Kh = g_Kh + base;
    const __nv_bfloat16* __restrict__ Kl = g_Kl + base;
    const __nv_bfloat16* __restrict__ Vh = g_Vh + base;
    const __nv_bfloat16* __restrict__ Vl = g_Vl + base;

    const int tid  = threadIdx.x;
    const int lane = tid & 31;
    const int warp = tid >> 5;
    const uint32_t smb = s2u(sm);

    auto issue_pair = [&](const __nv_bfloat16* Sh, const __nv_bfloat16* Sl,
                          uint32_t dstb, int j) {
        #pragma unroll
        for (int it = 0; it < 8; it++) {
            int s = it * 128 + tid;
            int half = s >> 9;
            int row = (s >> 3) & 63;
            int seg = s & 7;
            cpa16(dstb + (uint32_t)half * TILE_KV + (uint32_t)(row * TSTR_B + seg * 16),
                  (half ? Sl : Sh) + (size_t)(j * 64 + row) * DHH + seg * 8);
        }
        CPA_COMMIT();
    };

    #pragma unroll
    for (int it = 0; it < 4; it++) {
        int s = it * 128 + tid;
        int row = s >> 3, seg = s & 7;
        *(uint4*)(sm + row * TSTR_B + seg * 16) =
            *(const uint4*)(Qh + (size_t)(q0 + row) * DHH + seg * 8);
        *(uint4*)(sm + TILE_KV + row * TSTR_B + seg * 16) =
            *(const uint4*)(Ql + (size_t)(q0 + row) * DHH + seg * 8);
    }
    issue_pair(Kh, Kl, smb + OFF_KH, 0);
    issue_pair(Vh, Vl, smb + OFF_VH, 0);
    __syncthreads();

    uint32_t qfh[4][4], qfl[4][4];
    {
        uint32_t qa = smb + (uint32_t)((warp * 16 + (lane & 7) + ((lane >> 3) & 1) * 8) * TSTR_B
                                       + ((lane >> 4) & 1) * 16);
        #pragma unroll
        for (int ks = 0; ks < 4; ks++) {
            ldsm4(qfh[ks], qa + ks * 32);
            ldsm4(qfl[ks], qa + ks * 32 + TILE_KV);
        }
    }

    float o[8][4];
    #pragma unroll
    for (int nb = 0; nb < 8; nb++)
        #pragma unroll
        for (int r = 0; r < 4; r++) o[nb][r] = 0.f;
    float m0s = -CUDART_INF_F, m1s = -CUDART_INF_F, l0s = 0.f, l1s = 0.f;

    const int qlo = q0 + warp * 16 + (lane >> 2);
    const int qhi = qlo + 8;

    for (int j = 0; j <= qt; j++) {
        CPA_WAIT(1);              // K(j) ready; V(j) may be in flight
        __syncthreads();

        float c[8][4];
        #pragma unroll
        for (int nb = 0; nb < 8; nb++)
            #pragma unroll
            for (int r = 0; r < 4; r++) c[nb][r] = 0.f;

        #pragma unroll
        for (int ks = 0; ks < 4; ks++) {
            uint32_t kfh[4][4], kfl[4][4];
            #pragma unroll
            for (int p = 0; p < 4; p++) {
                uint32_t ka = smb + OFF_KH
                            + (uint32_t)((p * 16 + (lane & 7) + ((lane >> 4) & 1) * 8) * TSTR_B
                                         + ((lane >> 3) & 1) * 16 + ks * 32);
                ldsm4(kfh[p], ka);
                ldsm4(kfl[p], ka + TILE_KV);
            }
            #pragma unroll
            for (int p = 0; p < 4; p++)
                #pragma unroll
                for (int h2 = 0; h2 < 2; h2++) {
                    int nb = p * 2 + h2;
                    mma_bf16(c[nb], qfh[ks], &kfh[p][h2 * 2]);
                    mma_bf16(c[nb], qfh[ks], &kfl[p][h2 * 2]);
                    mma_bf16(c[nb], qfl[ks], &kfh[p][h2 * 2]);
                }
        }
        __syncthreads();
        if (j < qt) issue_pair(Kh, Kl, smb + OFF_KH, j + 1);

        const bool diag = (j == qt);
        float mx0 = -CUDART_INF_F, mx1 = -CUDART_INF_F;
        #pragma unroll
        for (int nb = 0; nb < 8; nb++) {
            #pragma unroll
            for (int r = 0; r < 4; r++) c[nb][r] *= 0.125f;
            if (diag) {
                int colb = j * 64 + nb * 8 + (lane & 3) * 2;
                if (colb     > qlo) c[nb][0] = -CUDART_INF_F;
                if (colb + 1 > qlo) c[nb][1] = -CUDART_INF_F;
                if (colb     > qhi) c[nb][2] = -CUDART_INF_F;
                if (colb + 1 > qhi) c[nb][3] = -CUDART_INF_F;
            }
            mx0 = fmaxf(mx0, fmaxf(c[nb][0], c[nb][1]));
            mx1 = fmaxf(mx1, fmaxf(c[nb][2], c[nb][3]));
        }
        mx0 = fmaxf(mx0, __shfl_xor_sync(0xffffffffu, mx0, 1));
        mx0 = fmaxf(mx0, __shfl_xor_sync(0xffffffffu, mx0, 2));
        mx1 = fmaxf(mx1, __shfl_xor_sync(0xffffffffu, mx1, 1));
        mx1 = fmaxf(mx1, __shfl_xor_sync(0xffffffffu, mx1, 2));

        const float mn0 = fmaxf(m0s, mx0), mn1 = fmaxf(m1s, mx1);
        float s0 = 0.f, s1 = 0.f;
        #pragma unroll
        for (int nb = 0; nb < 8; nb++) {
            c[nb][0] = __expf(c[nb][0] - mn0);
            c[nb][1] = __expf(c[nb][1] - mn0);
            c[nb][2] = __expf(c[nb][2] - mn1);
            c[nb][3] = __expf(c[nb][3] - mn1);
            s0 += c[nb][0] + c[nb][1];
            s1 += c[nb][2] + c[nb][3];
        }
        s0 += __shfl_xor_sync(0xffffffffu, s0, 1);
        s0 += __shfl_xor_sync(0xffffffffu, s0, 2);
        s1 += __shfl_xor_sync(0xffffffffu, s1, 1);
        s1 += __shfl_xor_sync(0xffffffffu, s1, 2);

        const float a0 = __expf(m0s - mn0), a1 = __expf(m1s - mn1);
        const float ln0 = a0 * l0s + s0, ln1 = a1 * l1s + s1;
        const float f0 = l0s / ln0 * a0, f1 = l1s / ln1 * a1;
        #pragma unroll
        for (int nb = 0; nb < 8; nb++) {
            o[nb][0] *= f0; o[nb][1] *= f0;
            o[nb][2] *= f1; o[nb][3] *= f1;
        }
        m0s = mn0; l0s = ln0; m1s = mn1; l1s = ln1;

        if (j < qt) { CPA_WAIT(1); } else { CPA_WAIT(0); }
        __syncthreads();

        #pragma unroll
        for (int ks = 0; ks < 4; ks++) {
            uint32_t pah[4], pal[4];
            split2(c[2 * ks][0],     c[2 * ks][1],     pah[0], pal[0]);
            split2(c[2 * ks][2],     c[2 * ks][3],     pah[1], pal[1]);
            split2(c[2 * ks + 1][0], c[2 * ks + 1][1], pah[2], pal[2]);
            split2(c[2 * ks + 1][2], c[2 * ks + 1][3], pah[3], pal[3]);

            uint32_t vfh[4][4], vfl[4][4];
            #pragma unroll
            for (int p = 0; p < 4; p++) {
                uint32_t va = smb + OFF_VH
                            + (uint32_t)((ks * 16 + (lane & 7) + ((lane >> 3) & 1) * 8) * TSTR_B
                                         + (p * 16 + ((lane >> 4) & 1) * 8) * 2);
                ldsm4t(vfh[p], va);
                ldsm4t(vfl[p], va + TILE_KV);
            }
            #pragma unroll
            for (int p = 0; p < 4; p++)
                #pragma unroll
                for (int h2 = 0; h2 < 2; h2++) {
                    int nb = p * 2 + h2;
                    mma_bf16(o[nb], pah, &vfh[p][h2 * 2]);
                    mma_bf16(o[nb], pah, &vfl[p][h2 * 2]);
                    mma_bf16(o[nb], pal, &vfh[p][h2 * 2]);
                }
        }
        __syncthreads();
        if (j < qt) issue_pair(Vh, Vl, smb + OFF_VH, j + 1);
    }

    const int b = bh >> 4, hq = bh & 15;
    #pragma unroll
    for (int nb = 0; nb < 8; nb++) {
        const int col = hq * 64 + nb * 8 + (lane & 3) * 2;
        uint32_t ph, pl;
        split2(o[nb][0], o[nb][1], ph, pl);
        size_t idx = ((size_t)b * SS + qlo) * DD + col;
        *(uint32_t*)(g_Oh + idx) = ph;
        *(uint32_t*)(g_Ol + idx) = pl;
        split2(o[nb][2], o[nb][3], ph, pl);
        idx = ((size_t)b * SS + qhi) * DD + col;
        *(uint32_t*)(g_Oh + idx) = ph;
        *(uint32_t*)(g_Ol + idx) = pl;
    }
}

// ---------------- launch ----------------
extern "C" void kernel_launch(void* const* d_in, const int* in_sizes, int n_in,
                              void* d_out, int out_size)
{
    const float* x  = (const float*)d_in[0];
    const float* Wq = (const float*)d_in[1];
    const float* bq = (const float*)d_in[2];
    const float* Wk = (const float*)d_in[3];
    const float* bk = (const float*)d_in[4];
    const float* Wv = (const float*)d_in[5];
    const float* bv = (const float*)d_in[6];
    const float* Wo = (const float*)d_in[7];
    const float* bo = (const float*)d_in[8];
    float* out = (float*)d_out;

    static bool attr_done = false;
    if (!attr_done) {
        cudaFuncSetAttribute(attn_tc,
                             cudaFuncAttributeMaxDynamicSharedMemorySize, ATT_SMEM);
        cudaFuncSetAttribute(proj_tc,
                             cudaFuncAttributeMaxDynamicSharedMemorySize, GEMM_SMEM);
        cudaFuncSetAttribute(outproj_tc,
                             cudaFuncAttributeMaxDynamicSharedMemorySize, GEMM_SMEM);
        attr_done = true;
    }

    split_x<<<(BB * SS * DD) / (256 * 4), 256>>>(x);
    transpose_split<<<dim3(DD / 32, DD / 32, 4), dim3(32, 8)>>>(Wq, Wk, Wv, Wo);
    proj_tc<<<dim3(DD / 128, (BB * SS) / 128, 3), 256, GEMM_SMEM>>>(bq, bk, bv);
    attn_tc<<<dim3(BB * HH, SS / 64), 128, ATT_SMEM>>>();
    outproj_tc<<<dim3(DD / 128, (BB * SS) / 128), 256, GEMM_SMEM>>>(bo, out);
}

// round 11
// speedup vs baseline: 1.0997x; 1.0184x over previous
#include <cuda_runtime.h>
#include <cuda_bf16.h>
#include <math_constants.h>
#include <cstdint>

#define BB  4
#define SS  2048
#define DD  1024
#define HH  16
#define DHH 64

// Q is pre-scaled by 1/sqrt(DH) * log2(e) so attention uses exp2 directly.
#define QSCALE 0.1803368801111204f   // 0.125 * 1.4426950408889634

// ---------------- scratch (device globals; no allocations) ----------------
__device__ __nv_bfloat16 g_xh[(size_t)BB * SS * DD];
__device__ __nv_bfloat16 g_xl[(size_t)BB * SS * DD];
__device__ __nv_bfloat16 g_WqTh[(size_t)DD * DD], g_WqTl[(size_t)DD * DD];
__device__ __nv_bfloat16 g_WkTh[(size_t)DD * DD], g_WkTl[(size_t)DD * DD];
__device__ __nv_bfloat16 g_WvTh[(size_t)DD * DD], g_WvTl[(size_t)DD * DD];
__device__ __nv_bfloat16 g_WoTh[(size_t)DD * DD], g_WoTl[(size_t)DD * DD];
__device__ __nv_bfloat16 g_Qh[(size_t)BB * HH * SS * DHH], g_Ql[(size_t)BB * HH * SS * DHH];
__device__ __nv_bfloat16 g_Kh[(size_t)BB * HH * SS * DHH], g_Kl[(size_t)BB * HH * SS * DHH];
__device__ __nv_bfloat16 g_Vh[(size_t)BB * HH * SS * DHH], g_Vl[(size_t)BB * HH * SS * DHH];
__device__ __nv_bfloat16 g_Oh[(size_t)BB * SS * DD];
__device__ __nv_bfloat16 g_Ol[(size_t)BB * SS * DD];

// ---------------- PTX helpers (sm_80+ only) ----------------
__device__ __forceinline__ uint32_t s2u(const void* p) {
    uint32_t a;
    asm("{ .reg .u64 t; cvta.to.shared.u64 t, %1; cvt.u32.u64 %0, t; }"
        : "=r"(a) : "l"(p));
    return a;
}
__device__ __forceinline__ void ldsm4(uint32_t* r, uint32_t addr) {
    asm volatile("ldmatrix.sync.aligned.m8n8.x4.shared.b16 {%0,%1,%2,%3}, [%4];"
        : "=r"(r[0]), "=r"(r[1]), "=r"(r[2]), "=r"(r[3]) : "r"(addr));
}
__device__ __forceinline__ void ldsm4t(uint32_t* r, uint32_t addr) {
    asm volatile("ldmatrix.sync.aligned.m8n8.x4.trans.shared.b16 {%0,%1,%2,%3}, [%4];"
        : "=r"(r[0]), "=r"(r[1]), "=r"(r[2]), "=r"(r[3]) : "r"(addr));
}
__device__ __forceinline__ void mma_bf16(float* d, const uint32_t* a, const uint32_t* b) {
    asm volatile(
        "mma.sync.aligned.m16n8k16.row.col.f32.bf16.bf16.f32 "
        "{%0,%1,%2,%3}, {%4,%5,%6,%7}, {%8,%9}, {%0,%1,%2,%3};"
        : "+f"(d[0]), "+f"(d[1]), "+f"(d[2]), "+f"(d[3])
        : "r"(a[0]), "r"(a[1]), "r"(a[2]), "r"(a[3]), "r"(b[0]), "r"(b[1]));
}
__device__ __forceinline__ void cpa16(uint32_t s, const void* g) {
    asm volatile("cp.async.cg.shared.global [%0], [%1], 16;" :: "r"(s), "l"(g));
}
#define CPA_COMMIT() asm volatile("cp.async.commit_group;" ::: "memory")
#define CPA_WAIT(n)  asm volatile("cp.async.wait_group %0;" :: "n"(n) : "memory")

__device__ __forceinline__ uint32_t packbf(float x, float y) {
    __nv_bfloat162 t = __floats2bfloat162_rn(x, y);
    return *(uint32_t*)&t;
}
__device__ __forceinline__ void split2(float a, float b, uint32_t& h, uint32_t& l) {
    float ha = __bfloat162float(__float2bfloat16(a));
    float hb = __bfloat162float(__float2bfloat16(b));
    h = packbf(ha, hb);
    l = packbf(a - ha, b - hb);
}

// ---------------- bf16 hi/lo split kernels ----------------
__global__ __launch_bounds__(256) void split_x(const float* __restrict__ x) {
    size_t i = ((size_t)blockIdx.x * 256 + threadIdx.x) * 4;
    float4 v = *(const float4*)(x + i);
    float vv[4] = {v.x, v.y, v.z, v.w};
    __nv_bfloat16 h[4], l[4];
    #pragma unroll
    for (int j = 0; j < 4; j++) {
        h[j] = __float2bfloat16(vv[j]);
        l[j] = __float2bfloat16(vv[j] - __bfloat162float(h[j]));
    }
    *(uint2*)(g_xh + i) = *(uint2*)h;
    *(uint2*)(g_xl + i) = *(uint2*)l;
}

__global__ void transpose_split(const float* __restrict__ Wq, const float* __restrict__ Wk,
                                const float* __restrict__ Wv, const float* __restrict__ Wo) {
    __shared__ float t[32][33];
    const int z = blockIdx.z;
    const float* W = (z == 0) ? Wq : (z == 1) ? Wk : (z == 2) ? Wv : Wo;
    __nv_bfloat16* Th = (z == 0) ? g_WqTh : (z == 1) ? g_WkTh : (z == 2) ? g_WvTh : g_WoTh;
    __nv_bfloat16* Tl = (z == 0) ? g_WqTl : (z == 1) ? g_WkTl : (z == 2) ? g_WvTl : g_WoTl;
    const int n0 = blockIdx.x * 32, k0 = blockIdx.y * 32;
    const int tx = threadIdx.x, ty = threadIdx.y;
    #pragma unroll
    for (int j = 0; j < 32; j += 8)
        t[ty + j][tx] = W[(size_t)(k0 + ty + j) * DD + n0 + tx];
    __syncthreads();
    #pragma unroll
    for (int j = 0; j < 32; j += 8) {
        float v = t[tx][ty + j];
        int n = n0 + ty + j, k = k0 + tx;
        __nv_bfloat16 h = __float2bfloat16(v);
        __nv_bfloat16 l = __float2bfloat16(v - __bfloat162float(h));
        Th[(size_t)n * DD + k] = h;
        Tl[(size_t)n * DD + k] = l;
    }
}

// ---------------- mma.sync GEMM: 128x128 tile, bf16x3, cp.async ------------
#define KCH     32
#define NCHUNK  (DD / KCH)
#define RSTR    40
#define TILE_B  (128 * RSTR * 2)
#define BUF_B   (4 * TILE_B)
#define GEMM_SMEM (2 * BUF_B)

__device__ __forceinline__ void gemm_loop(
    const __nv_bfloat16* __restrict__ Ah, const __nv_bfloat16* __restrict__ Al,
    const __nv_bfloat16* __restrict__ Bh, const __nv_bfloat16* __restrict__ Bl,
    int m0, int n0, char* sm, float acc[4][4][4])
{
    const int tid  = threadIdx.x;
    const int lane = tid & 31;
    const int warp = tid >> 5;
    const int wm   = warp & 1;
    const int wn   = warp >> 1;

    const uint32_t sb = s2u(sm);
    const int a_row  = wm * 64 + (lane & 7) + ((lane >> 3) & 1) * 8;
    const int a_kof  = (lane >> 4) * 8;
    const int b_row4 = wn * 32 + (lane & 7) + ((lane >> 4) & 1) * 8;
    const int b_kof4 = ((lane >> 3) & 1) * 8;

    auto issue = [&](int k0, uint32_t dstb) {
        #pragma unroll
        for (int it = 0; it < 8; it++) {
            int gid  = it * 256 + tid;
            int tile = gid >> 9;
            int row  = (gid >> 2) & 127;
            int seg  = gid & 3;
            const __nv_bfloat16* src = (tile == 0) ? Ah : (tile == 1) ? Al
                                     : (tile == 2) ? Bh : Bl;
            int rb = (tile < 2) ? m0 : n0;
            cpa16(dstb + (uint32_t)tile * TILE_B + (uint32_t)(row * RSTR + seg * 8) * 2,
                  src + (size_t)(rb + row) * DD + k0 + seg * 8);
        }
        CPA_COMMIT();
    };

    issue(0, sb);

    for (int c = 0; c < NCHUNK; c++) {
        CPA_WAIT(0);
        __syncthreads();
        if (c + 1 < NCHUNK)
            issue((c + 1) * KCH, sb + (uint32_t)((c + 1) & 1) * BUF_B);

        const uint32_t bufb = sb + (uint32_t)(c & 1) * BUF_B;
        #pragma unroll
        for (int ks = 0; ks < 2; ks++) {
            uint32_t fbh[4][2], fbl[4][2];
            #pragma unroll
            for (int nip = 0; nip < 2; nip++) {
                uint32_t bo = bufb + (uint32_t)(((b_row4 + nip * 16) * RSTR) + ks * 16 + b_kof4) * 2;
                uint32_t t4[4];
                ldsm4(t4, bo + 2 * TILE_B);
                fbh[nip * 2][0] = t4[0]; fbh[nip * 2][1] = t4[1];
                fbh[nip * 2 + 1][0] = t4[2]; fbh[nip * 2 + 1][1] = t4[3];
                ldsm4(t4, bo + 3 * TILE_B);
                fbl[nip * 2][0] = t4[0]; fbl[nip * 2][1] = t4[1];
                fbl[nip * 2 + 1][0] = t4[2]; fbl[nip * 2 + 1][1] = t4[3];
            }
            #pragma unroll
            for (int mi = 0; mi < 4; mi++) {
                uint32_t fah[4], fal[4];
                uint32_t ao = bufb + (uint32_t)(((a_row + mi * 16) * RSTR) + ks * 16 + a_kof) * 2;
                ldsm4(fah, ao);
                ldsm4(fal, ao + TILE_B);
                #pragma unroll
                for (int ni = 0; ni < 4; ni++) {
                    mma_bf16(acc[mi][ni], fah, fbh[ni]);
                    mma_bf16(acc[mi][ni], fah, fbl[ni]);
                    mma_bf16(acc[mi][ni], fal, fbh[ni]);
                }
            }
        }
    }
}

// ---------------- projection GEMMs (Q/K/V) -> bf16 hi/lo ----------------
__global__ __launch_bounds__(256, 2) void proj_tc(const float* __restrict__ bq,
                                                  const float* __restrict__ bk,
                                                  const float* __restrict__ bv)
{
    extern __shared__ char sm[];
    const int z = blockIdx.z;
    const __nv_bfloat16* Bh = (z == 0) ? g_WqTh : (z == 1) ? g_WkTh : g_WvTh;
    const __nv_bfloat16* Bl = (z == 0) ? g_WqTl : (z == 1) ? g_WkTl : g_WvTl;
    const float* bias       = (z == 0) ? bq : (z == 1) ? bk : bv;
    __nv_bfloat16* Oh       = (z == 0) ? g_Qh : (z == 1) ? g_Kh : g_Vh;
    __nv_bfloat16* Ol       = (z == 0) ? g_Ql : (z == 1) ? g_Kl : g_Vl;
    const float scale       = (z == 0) ? QSCALE : 1.0f;

    const int m0 = blockIdx.y * 128;
    const int n0 = blockIdx.x * 128;

    float acc[4][4][4];
    #pragma unroll
    for (int mi = 0; mi < 4; mi++)
        #pragma unroll
        for (int ni = 0; ni < 4; ni++)
            #pragma unroll
            for (int k = 0; k < 4; k++) acc[mi][ni][k] = 0.f;

    gemm_loop(g_xh, g_xl, Bh, Bl, m0, n0, sm, acc);

    const int lane = threadIdx.x & 31;
    const int warp = threadIdx.x >> 5;
    const int wm = warp & 1, wn = warp >> 1;

    #pragma unroll
    for (int ni = 0; ni < 4; ni++) {
        const int gn = n0 + wn * 32 + ni * 8 + (lane & 3) * 2;
        const int h = gn >> 6, dh = gn & 63;
        const float b0 = bias[gn], b1 = bias[gn + 1];
        #pragma unroll
        for (int mi = 0; mi < 4; mi++) {
            const int gm = m0 + wm * 64 + mi * 16 + (lane >> 2);
            #pragma unroll
            for (int rh = 0; rh < 2; rh++) {
                const int m = gm + rh * 8;
                const int bidx = m >> 11, s = m & 2047;
                float vx = (acc[mi][ni][rh * 2 + 0] + b0) * scale;
                float vy = (acc[mi][ni][rh * 2 + 1] + b1) * scale;
                uint32_t uh, ul;
                split2(vx, vy, uh, ul);
                size_t idx = (((size_t)bidx * HH + h) * SS + s) * DHH + dh;
                *(uint32_t*)(Oh + idx) = uh;
                *(uint32_t*)(Ol + idx) = ul;
            }
        }
    }
}

// ---------------- output projection ----------------
__global__ __launch_bounds__(256, 2) void outproj_tc(const float* __restrict__ bo,
                                                     float* __restrict__ out)
{
    extern __shared__ char sm[];
    const int m0 = blockIdx.y * 128;
    const int n0 = blockIdx.x * 128;

    float acc[4][4][4];
    #pragma unroll
    for (int mi = 0; mi < 4; mi++)
        #pragma unroll
        for (int ni = 0; ni < 4; ni++)
            #pragma unroll
            for (int k = 0; k < 4; k++) acc[mi][ni][k] = 0.f;

    gemm_loop(g_Oh, g_Ol, g_WoTh, g_WoTl, m0, n0, sm, acc);

    const int lane = threadIdx.x & 31;
    const int warp = threadIdx.x >> 5;
    const int wm = warp & 1, wn = warp >> 1;

    #pragma unroll
    for (int ni = 0; ni < 4; ni++) {
        const int gn = n0 + wn * 32 + ni * 8 + (lane & 3) * 2;
        const float b0 = bo[gn], b1 = bo[gn + 1];
        #pragma unroll
        for (int mi = 0; mi < 4; mi++) {
            const int gm = m0 + wm * 64 + mi * 16 + (lane >> 2);
            #pragma unroll
            for (int rh = 0; rh < 2; rh++) {
                const int m = gm + rh * 8;
                float2 v;
                v.x = acc[mi][ni][rh * 2 + 0] + b0;
                v.y = acc[mi][ni][rh * 2 + 1] + b1;
                *(float2*)(out + (size_t)m * DD + gn) = v;
            }
        }
    }
}

// ---------------- tensor-core attention, faithful recurrence ----------------
// Heavy-first grid; 4 CTAs/SM target: regs<=128 (Q frags reloaded from smem,
// K/V fragments consumed in 8-register bursts), exp2-domain softmax.
#define TSTR_B   144
#define TILE_KV  (64 * TSTR_B)        // 9216
#define OFF_KH   (2 * TILE_KV)
#define OFF_VH   (4 * TILE_KV)
#define ATT_SMEM (6 * TILE_KV)        // 55296

__global__ __launch_bounds__(128, 4) void attn_tc()
{
    extern __shared__ char sm[];
    const int qt = (int)gridDim.y - 1 - (int)blockIdx.y;
    const int q0 = qt * 64;
    const int bh = blockIdx.x;
    const size_t base = (size_t)bh * SS * DHH;
    const __nv_bfloat16* __restrict__ Qh = g_Qh + base;
    const __nv_bfloat16* __restrict__ Ql = g_Ql + base;
    const __nv_bfloat16* __restrict__ Kh = g_Kh + base;
    const __nv_bfloat16* __restrict__ Kl = g_Kl + base;
    const __nv_bfloat16* __restrict__ Vh = g_Vh + base;
    const __nv_bfloat16* __restrict__ Vl = g_Vl + base;

    const int tid  = threadIdx.x;
    const int lane = tid & 31;
    const int warp = tid >> 5;
    const uint32_t smb = s2u(sm);

    auto issue_pair = [&](const __nv_bfloat16* Sh, const __nv_bfloat16* Sl,
                          uint32_t dstb, int j) {
        #pragma unroll
        for (int it = 0; it < 8; it++) {
            int s = it * 128 + tid;
            int half = s >> 9;
            int row = (s >> 3) & 63;
            int seg = s & 7;
            cpa16(dstb + (uint32_t)half * TILE_KV + (uint32_t)(row * TSTR_B + seg * 16),
                  (half ? Sl : Sh) + (size_t)(j * 64 + row) * DHH + seg * 8);
        }
        CPA_COMMIT();
    };

    #pragma unroll
    for (int it = 0; it < 4; it++) {
        int s = it * 128 + tid;
        int row = s >> 3, seg = s & 7;
        *(uint4*)(sm + row * TSTR_B + seg * 16) =
            *(const uint4*)(Qh + (size_t)(q0 + row) * DHH + seg * 8);
        *(uint4*)(sm + TILE_KV + row * TSTR_B + seg * 16) =
            *(const uint4*)(Ql + (size_t)(q0 + row) * DHH + seg * 8);
    }
    issue_pair(Kh, Kl, smb + OFF_KH, 0);
    issue_pair(Vh, Vl, smb + OFF_VH, 0);
    __syncthreads();

    const uint32_t qa = smb + (uint32_t)((warp * 16 + (lane & 7) + ((lane >> 3) & 1) * 8) * TSTR_B
                                         + ((lane >> 4) & 1) * 16);

    float o[8][4];
    #pragma unroll
    for (int nb = 0; nb < 8; nb++)
        #pragma unroll
        for (int r = 0; r < 4; r++) o[nb][r] = 0.f;
    float m0s = -CUDART_INF_F, m1s = -CUDART_INF_F, l0s = 0.f, l1s = 0.f;

    const int qlo = q0 + warp * 16 + (lane >> 2);
    const int qhi = qlo + 8;

    for (int j = 0; j <= qt; j++) {
        CPA_WAIT(1);              // K(j) ready; V(j) may be in flight
        __syncthreads();

        float c[8][4];
        #pragma unroll
        for (int nb = 0; nb < 8; nb++)
            #pragma unroll
            for (int r = 0; r < 4; r++) c[nb][r] = 0.f;

        #pragma unroll
        for (int ks = 0; ks < 4; ks++) {
            uint32_t qh4[4], ql4[4];
            ldsm4(qh4, qa + ks * 32);
            ldsm4(ql4, qa + ks * 32 + TILE_KV);
            #pragma unroll
            for (int p = 0; p < 4; p++) {
                uint32_t ka = smb + OFF_KH
                            + (uint32_t)((p * 16 + (lane & 7) + ((lane >> 4) & 1) * 8) * TSTR_B
                                         + ((lane >> 3) & 1) * 16 + ks * 32);
                uint32_t kh4[4], kl4[4];
                ldsm4(kh4, ka);
                ldsm4(kl4, ka + TILE_KV);
                #pragma unroll
                for (int h2 = 0; h2 < 2; h2++) {
                    int nb = p * 2 + h2;
                    mma_bf16(c[nb], qh4, &kh4[h2 * 2]);
                    mma_bf16(c[nb], qh4, &kl4[h2 * 2]);
                    mma_bf16(c[nb], ql4, &kh4[h2 * 2]);
                }
            }
        }
        __syncthreads();
        if (j < qt) issue_pair(Kh, Kl, smb + OFF_KH, j + 1);

        // softmax recurrence in exp2 domain (Q pre-scaled by 0.125*log2e)
        const bool diag = (j == qt);
        float mx0 = -CUDART_INF_F, mx1 = -CUDART_INF_F;
        #pragma unroll
        for (int nb = 0; nb < 8; nb++) {
            if (diag) {
                int colb = j * 64 + nb * 8 + (lane & 3) * 2;
                if (colb     > qlo) c[nb][0] = -CUDART_INF_F;
                if (colb + 1 > qlo) c[nb][1] = -CUDART_INF_F;
                if (colb     > qhi) c[nb][2] = -CUDART_INF_F;
                if (colb + 1 > qhi) c[nb][3] = -CUDART_INF_F;
            }
            mx0 = fmaxf(mx0, fmaxf(c[nb][0], c[nb][1]));
            mx1 = fmaxf(mx1, fmaxf(c[nb][2], c[nb][3]));
        }
        mx0 = fmaxf(mx0, __shfl_xor_sync(0xffffffffu, mx0, 1));
        mx0 = fmaxf(mx0, __shfl_xor_sync(0xffffffffu, mx0, 2));
        mx1 = fmaxf(mx1, __shfl_xor_sync(0xffffffffu, mx1, 1));
        mx1 = fmaxf(mx1, __shfl_xor_sync(0xffffffffu, mx1, 2));

        const float mn0 = fmaxf(m0s, mx0), mn1 = fmaxf(m1s, mx1);
        float s0 = 0.f, s1 = 0.f;
        #pragma unroll
        for (int nb = 0; nb < 8; nb++) {
            c[nb][0] = exp2f(c[nb][0] - mn0);
            c[nb][1] = exp2f(c[nb][1] - mn0);
            c[nb][2] = exp2f(c[nb][2] - mn1);
            c[nb][3] = exp2f(c[nb][3] - mn1);
            s0 += c[nb][0] + c[nb][1];
            s1 += c[nb][2] + c[nb][3];
        }
        s0 += __shfl_xor_sync(0xffffffffu, s0, 1);
        s0 += __shfl_xor_sync(0xffffffffu, s0, 2);
        s1 += __shfl_xor_sync(0xffffffffu, s1, 1);
        s1 += __shfl_xor_sync(0xffffffffu, s1, 2);

        const float a0 = exp2f(m0s - mn0), a1 = exp2f(m1s - mn1);
        const float ln0 = a0 * l0s + s0, ln1 = a1 * l1s + s1;
        const float f0 = l0s / ln0 * a0, f1 = l1s / ln1 * a1;
        #pragma unroll
        for (int nb = 0; nb < 8; nb++) {
            o[nb][0] *= f0; o[nb][1] *= f0;
            o[nb][2] *= f1; o[nb][3] *= f1;
        }
        m0s = mn0; l0s = ln0; m1s = mn1; l1s = ln1;

        if (j < qt) { CPA_WAIT(1); } else { CPA_WAIT(0); }
        __syncthreads();

        #pragma unroll
        for (int ks = 0; ks < 4; ks++) {
            uint32_t pah[4], pal[4];
            split2(c[2 * ks][0],     c[2 * ks][1],     pah[0], pal[0]);
            split2(c[2 * ks][2],     c[2 * ks][3],     pah[1], pal[1]);
            split2(c[2 * ks + 1][0], c[2 * ks + 1][1], pah[2], pal[2]);
            split2(c[2 * ks + 1][2], c[2 * ks + 1][3], pah[3], pal[3]);

            #pragma unroll
            for (int p = 0; p < 4; p++) {
                uint32_t va = smb + OFF_VH
                            + (uint32_t)((ks * 16 + (lane & 7) + ((lane >> 3) & 1) * 8) * TSTR_B
                                         + (p * 16 + ((lane >> 4) & 1) * 8) * 2);
                uint32_t vh4[4], vl4[4];
                ldsm4t(vh4, va);
                ldsm4t(vl4, va + TILE_KV);
                #pragma unroll
                for (int h2 = 0; h2 < 2; h2++) {
                    int nb = p * 2 + h2;
                    mma_bf16(o[nb], pah, &vh4[h2 * 2]);
                    mma_bf16(o[nb], pah, &vl4[h2 * 2]);
                    mma_bf16(o[nb], pal, &vh4[h2 * 2]);
                }
            }
        }
        __syncthreads();
        if (j < qt) issue_pair(Vh, Vl, smb + OFF_VH, j + 1);
    }

    const int b = bh >> 4, hq = bh & 15;
    #pragma unroll
    for (int nb = 0; nb < 8; nb++) {
        const int col = hq * 64 + nb * 8 + (lane & 3) * 2;
        uint32_t ph, pl;
        split2(o[nb][0], o[nb][1], ph, pl);
        size_t idx = ((size_t)b * SS + qlo) * DD + col;
        *(uint32_t*)(g_Oh + idx) = ph;
        *(uint32_t*)(g_Ol + idx) = pl;
        split2(o[nb][2], o[nb][3], ph, pl);
        idx = ((size_t)b * SS + qhi) * DD + col;
        *(uint32_t*)(g_Oh + idx) = ph;
        *(uint32_t*)(g_Ol + idx) = pl;
    }
}

// ---------------- launch ----------------
extern "C" void kernel_launch(void* const* d_in, const int* in_sizes, int n_in,
                              void* d_out, int out_size)
{
    const float* x  = (const float*)d_in[0];
    const float* Wq = (const float*)d_in[1];
    const float* bq = (const float*)d_in[2];
    const float* Wk = (const float*)d_in[3];
    const float* bk = (const float*)d_in[4];
    const float* Wv = (const float*)d_in[5];
    const float* bv = (const float*)d_in[6];
    const float* Wo = (const float*)d_in[7];
    const float* bo = (const float*)d_in[8];
    float* out = (float*)d_out;

    static bool attr_done = false;
    if (!attr_done) {
        cudaFuncSetAttribute(attn_tc,
                             cudaFuncAttributeMaxDynamicSharedMemorySize, ATT_SMEM);
        cudaFuncSetAttribute(proj_tc,
                             cudaFuncAttributeMaxDynamicSharedMemorySize, GEMM_SMEM);
        cudaFuncSetAttribute(outproj_tc,
                             cudaFuncAttributeMaxDynamicSharedMemorySize, GEMM_SMEM);
        attr_done = true;
    }

    split_x<<<(BB * SS * DD) / (256 * 4), 256>>>(x);
    transpose_split<<<dim3(DD / 32, DD / 32, 4), dim3(32, 8)>>>(Wq, Wk, Wv, Wo);
    proj_tc<<<dim3(DD / 128, (BB * SS) / 128, 3), 256, GEMM_SMEM>>>(bq, bk, bv);
    attn_tc<<<dim3(BB * HH, SS / 64), 128, ATT_SMEM>>>();
    outproj_tc<<<dim3(DD / 128, (BB * SS) / 128), 256, GEMM_SMEM>>>(bo, out);
}